// round 14
// baseline (speedup 1.0000x reference)
#include <cuda_runtime.h>
#include <cstdint>

#define Nn 8192
#define Dd 1024

// Persistent scratch. g_pre[j] = PRE-activation of skips[j], j=0..7.
__device__ float g_pre[8][32][Dd];
// Packed adjacency: word (grp*4 + c), bit L  <=>  adj[n][grp*128 + 4L + c] != 0
__device__ uint32_t g_pm[Nn][256];            // 8 MB

#define APW 20   // uint32 words per bf16 tile row (16 data + 4 pad)

// Dynamic-smem workspace (58368 B -> 3 blocks/SM).
struct SmemP {
    uint32_t Ah[128 * APW];
    uint32_t Al[128 * APW];
    uint32_t Bh[32 * APW];
    uint32_t Bl[32 * APW];
    float    Wraw[2][128 * 32];
};
#define SMP_BYTES sizeof(SmemP)

__device__ __forceinline__ float sig(float v) {
    return 1.f / (1.f + __expf(-v));
}
__device__ __forceinline__ void redadd(float* p, float v) {
    asm volatile("red.global.add.f32 [%0], %1;" :: "l"(p), "f"(v) : "memory");
}
__device__ __forceinline__ uint32_t s2u(const void* p) {
    return (uint32_t)__cvta_generic_to_shared(p);
}
__device__ __forceinline__ void cpa16(uint32_t dst, const void* src) {
    asm volatile("cp.async.cg.shared.global [%0], [%1], 16;" :: "r"(dst), "l"(src));
}
__device__ __forceinline__ uint32_t pk2(float e1, float e0) {
    uint32_t r;
    asm("cvt.rn.bf16x2.f32 %0, %1, %2;" : "=r"(r) : "f"(e1), "f"(e0));
    return r;
}
__device__ __forceinline__ float lo_f(uint32_t r) { return __uint_as_float(r << 16); }
__device__ __forceinline__ float hi_f(uint32_t r) { return __uint_as_float(r & 0xFFFF0000u); }

__device__ __forceinline__ void split_store(uint32_t* Hp, uint32_t* Lp, float4 v) {
    uint32_t h01 = pk2(v.y, v.x);
    uint32_t h23 = pk2(v.w, v.z);
    float l0 = v.x - lo_f(h01), l1 = v.y - hi_f(h01);
    float l2 = v.z - lo_f(h23), l3 = v.w - hi_f(h23);
    *(uint2*)Hp = make_uint2(h01, h23);
    *(uint2*)Lp = make_uint2(pk2(l1, l0), pk2(l3, l2));
}

__device__ __forceinline__ void mma16(float* c,
                                      uint32_t a0, uint32_t a1, uint32_t a2, uint32_t a3,
                                      uint32_t b0, uint32_t b1) {
    asm volatile("mma.sync.aligned.m16n8k16.row.col.f32.bf16.bf16.f32 "
                 "{%0,%1,%2,%3}, {%4,%5,%6,%7}, {%8,%9}, {%0,%1,%2,%3};"
                 : "+f"(c[0]), "+f"(c[1]), "+f"(c[2]), "+f"(c[3])
                 : "r"(a0), "r"(a1), "r"(a2), "r"(a3), "r"(b0), "r"(b1));
}

// ---------------------------------------------------------------------------
// adj (int32) -> packed bitmask words. Block = one row, 8 warps x 8 passes.
// Each warp pass: lane reads int4 (coalesced 512B), 4 ballots, lane0 stores
// a uint4 of mask words. Layout matches consumer decode exactly.
// ---------------------------------------------------------------------------
__global__ void pack_kernel(const int* __restrict__ adj) {
    int n = blockIdx.x;
    int wid = threadIdx.x >> 5, lane = threadIdx.x & 31;
#pragma unroll
    for (int pass = 0; pass < 8; pass++) {
        int grp = pass * 8 + wid;               // 0..63 (128-col groups)
        int col = grp * 128 + lane * 4;
        int4 av = *(const int4*)&adj[(size_t)n * Nn + col];
        uint32_t b0 = __ballot_sync(0xFFFFFFFFu, av.x != 0);
        uint32_t b1 = __ballot_sync(0xFFFFFFFFu, av.y != 0);
        uint32_t b2 = __ballot_sync(0xFFFFFFFFu, av.z != 0);
        uint32_t b3 = __ballot_sync(0xFFFFFFFFu, av.w != 0);
        if (lane == 0)
            *(uint4*)&g_pm[n][grp * 4] = make_uint4(b0, b1, b2, b3);
    }
}

// ---------------------------------------------------------------------------
// Masked matvec via mma.sync bf16 hi/lo split, chunk-pipelined, pm masks:
//   out[b, d0+d] += sum_n act(X[b,n]) * W[d0+d,n] * mask(mrow+n, mcol+d0+d)
// ---------------------------------------------------------------------------
template <bool SIG>
__device__ __forceinline__ void mv_mma(
    SmemP* sm,
    const float* __restrict__ W, int wstride,
    int mrow, int mcol,
    const float* __restrict__ X, int xstride,
    float* __restrict__ out,
    int d0, int n0, int nchunks)
{
    const int tid  = threadIdx.x;
    const int wid  = tid >> 5, lane = tid & 31;
    const int g    = lane >> 2, tg = lane & 3;
    const int mw   = wid * 16;
    const int kq   = tid & 7;
    const int dw   = tid >> 3;
    const int jc   = dw & 3;
    const int bsh  = dw >> 2;
    const int mwidx = ((mcol + d0) >> 7) * 4 + jc;

    float c[4][4];
#pragma unroll
    for (int i = 0; i < 4; i++)
#pragma unroll
        for (int q = 0; q < 4; q++) c[i][q] = 0.f;

    uint32_t mcur[4], mnext[4];
    float4 xcur, xnext;

    {   // prologue: chunk 0 (W cp.async; masks + X via LDG)
        const int nb = n0;
#pragma unroll
        for (int p = 0; p < 4; p++) {
            int d = p * 32 + dw;
            cpa16(s2u(&sm->Wraw[0][d * 32 + kq * 4]),
                  &W[(size_t)(d0 + d) * wstride + nb + kq * 4]);
        }
        asm volatile("cp.async.commit_group;");
#pragma unroll
        for (int q = 0; q < 4; q++)
            mcur[q] = g_pm[mrow + nb + kq * 4 + q][mwidx];
        xcur = *(const float4*)&X[(size_t)dw * xstride + nb + kq * 4];
    }

    for (int ch = 0; ch < nchunks; ch++) {
        const int buf = ch & 1;
        const bool more = (ch + 1 < nchunks);

        if (more) {
            const int nb2 = n0 + (ch + 1) * 32;
#pragma unroll
            for (int p = 0; p < 4; p++) {
                int d = p * 32 + dw;
                cpa16(s2u(&sm->Wraw[buf ^ 1][d * 32 + kq * 4]),
                      &W[(size_t)(d0 + d) * wstride + nb2 + kq * 4]);
            }
            asm volatile("cp.async.commit_group;");
#pragma unroll
            for (int q = 0; q < 4; q++)
                mnext[q] = g_pm[mrow + nb2 + kq * 4 + q][mwidx];
            xnext = *(const float4*)&X[(size_t)dw * xstride + nb2 + kq * 4];
            asm volatile("cp.async.wait_group 1;");
        } else {
            asm volatile("cp.async.wait_group 0;");
        }
        __syncthreads();   // W[ch] landed; previous MMA done reading planes

        // ---- staging: mask raw W via packed bits, split to bf16 planes ----
#pragma unroll
        for (int p = 0; p < 4; p++) {
            int d = p * 32 + dw;
            int bp = p * 8 + bsh;        // = (d - dw%4)/4 within the group
            float4 w = *(const float4*)&sm->Wraw[buf][d * 32 + kq * 4];
            if (!((mcur[0] >> bp) & 1u)) w.x = 0.f;
            if (!((mcur[1] >> bp) & 1u)) w.y = 0.f;
            if (!((mcur[2] >> bp) & 1u)) w.z = 0.f;
            if (!((mcur[3] >> bp) & 1u)) w.w = 0.f;
            split_store(&sm->Ah[d * APW + kq * 2], &sm->Al[d * APW + kq * 2], w);
        }
        {
            float4 xv = xcur;
            if (SIG) {
                xv.x = sig(xv.x); xv.y = sig(xv.y);
                xv.z = sig(xv.z); xv.w = sig(xv.w);
            }
            split_store(&sm->Bh[dw * APW + kq * 2], &sm->Bl[dw * APW + kq * 2], xv);
        }
        __syncthreads();

        // ---- MMA phase: 2 k16-steps x 4 n-tiles x (hh + hl + lh) ----
#pragma unroll
        for (int ks = 0; ks < 2; ks++) {
            int u  = ks * 8 + tg;
            int r0 = (mw + g) * APW, r1 = (mw + g + 8) * APW;
            uint32_t ah0 = sm->Ah[r0 + u],     ah1 = sm->Ah[r1 + u];
            uint32_t ah2 = sm->Ah[r0 + u + 4], ah3 = sm->Ah[r1 + u + 4];
            uint32_t al0 = sm->Al[r0 + u],     al1 = sm->Al[r1 + u];
            uint32_t al2 = sm->Al[r0 + u + 4], al3 = sm->Al[r1 + u + 4];
#pragma unroll
            for (int nt = 0; nt < 4; nt++) {
                int bb = (nt * 8 + g) * APW + u;
                uint32_t bh0 = sm->Bh[bb], bh1 = sm->Bh[bb + 4];
                uint32_t bl0 = sm->Bl[bb], bl1 = sm->Bl[bb + 4];
                mma16(c[nt], ah0, ah1, ah2, ah3, bh0, bh1);
                mma16(c[nt], ah0, ah1, ah2, ah3, bl0, bl1);
                mma16(c[nt], al0, al1, al2, al3, bh0, bh1);
            }
        }

        if (more) {
#pragma unroll
            for (int q = 0; q < 4; q++) mcur[q] = mnext[q];
            xcur = xnext;
        }
    }

    const int drow = d0 + mw + g;
#pragma unroll
    for (int nt = 0; nt < 4; nt++) {
        int b = nt * 8 + 2 * tg;
        redadd(&out[(size_t)b       * Dd + drow],     c[nt][0]);
        redadd(&out[(size_t)(b + 1) * Dd + drow],     c[nt][1]);
        redadd(&out[(size_t)b       * Dd + drow + 8], c[nt][2]);
        redadd(&out[(size_t)(b + 1) * Dd + drow + 8], c[nt][3]);
    }
}

// ---------------------------------------------------------------------------

// g_pre[0][b][:] = b_in; g_pre[i][b][:] = b_h[i-1] for i=1..7  (float4)
__global__ void init_kernel(const float* __restrict__ b_in,
                            const float* __restrict__ b_h) {
    int idx = blockIdx.x * 256 + threadIdx.x;   // 256 blocks -> 65536 float4
    int fd = idx & 255;
    int i = idx >> 13;
    const float4* src = (i == 0) ? (const float4*)b_in
                                 : (const float4*)(b_h + (size_t)(i - 1) * Dd);
    ((float4*)g_pre)[idx] = src[fd];
}

// pre[k] += h @ Wr_m(k).T  (n >= (k+1)*1024). grid (8, (7-k)*8), nch=4.
__global__ void __launch_bounds__(256, 3) Wr_kernel(
    const float* __restrict__ W_r, const float* __restrict__ h, int k)
{
    extern __shared__ __align__(16) char dsm[];
    mv_mma<false>((SmemP*)dsm, W_r + (size_t)k * Dd * Nn, Nn,
                  0, k * 1024, h, Nn, &g_pre[k][0][0],
                  blockIdx.x * 128, (k + 1) * 1024 + blockIdx.y * 128, 4);
}

// g_pre[0] += x @ W_in.T  (atomic -> may overlap Wr_0 / pack)
__global__ void prelayer_kernel(
    const float* __restrict__ x, const float* __restrict__ W_in)
{
    int idx = blockIdx.x * 256 + threadIdx.x;  // 32768
    int d = idx & 1023, bt = idx >> 10;
    const float4* xr = (const float4*)(x + bt * 256);
    const float4* wr = (const float4*)(W_in + (size_t)d * 256);
    float s = 0.f;
#pragma unroll 8
    for (int c = 0; c < 64; c++) {
        float4 aa = xr[c], bb = wr[c];
        s += aa.x * bb.x + aa.y * bb.y + aa.z * bb.z + aa.w * bb.w;
    }
    redadd(&g_pre[0][bt][d], s);
}

// Serial-chain launch after pre[j] complete. grid (8, (7-j)*ksl):
//   g == 0        : pre[j+1] += sig(pre[j]) @ Wh_m(j).T
//   g in [1, 7-j) : pre[i+1] += sig(pre[j]) @ Ws-block(i, j).T  (i = j+g)
__global__ void __launch_bounds__(256, 3) Lp_kernel(
    const float* __restrict__ W_h, const float* __restrict__ W_s,
    int j, int nch, int ksl)
{
    extern __shared__ __align__(16) char dsm[];
    SmemP* sm = (SmemP*)dsm;
    int d0 = blockIdx.x * 128;
    int g = blockIdx.y / ksl;
    int nloc = (blockIdx.y % ksl) * 32 * nch;
    if (g == 0) {
        mv_mma<true>(sm, W_h + (size_t)j * Dd * Dd, Dd,
                     j * 1024, (j + 1) * 1024,
                     &g_pre[j][0][0], Dd,
                     &g_pre[j + 1][0][0], d0, nloc, nch);
    } else {
        int i = j + g;
        // X rebased so X[b*Dd + n] == g_pre[j][b][n - j*1024]
        mv_mma<true>(sm, W_s + (size_t)(i - 1) * Dd * 6144, 6144,
                     0, (i + 1) * 1024,
                     &g_pre[j][0][0] - j * 1024, Dd,
                     &g_pre[i + 1][0][0], d0, j * 1024 + nloc, nch);
    }
}

// out = sig(g_pre[7]) @ W_o.T + b_o
__global__ void final_kernel(const float* __restrict__ W_o,
                             const float* __restrict__ b_o,
                             float* __restrict__ out)
{
    int idx = blockIdx.x * 256 + threadIdx.x;  // 2048
    int o = idx & 63, bt = idx >> 6;
    const float4* sr = (const float4*)&g_pre[7][bt][0];
    const float4* wr = (const float4*)(W_o + (size_t)o * Dd);
    float s = 0.f;
#pragma unroll 8
    for (int c = 0; c < 256; c++) {
        float4 aa = sr[c], bb = wr[c];
        s += sig(aa.x) * bb.x + sig(aa.y) * bb.y + sig(aa.z) * bb.z + sig(aa.w) * bb.w;
    }
    out[bt * 64 + o] = s + b_o[o];
}

// ---------------------------------------------------------------------------

extern "C" void kernel_launch(void* const* d_in, const int* in_sizes, int n_in,
                              void* d_out, int out_size)
{
    const float* x    = (const float*)d_in[0];
    const float* h    = (const float*)d_in[1];
    const int*   adj  = (const int*)d_in[2];
    const float* W_in = (const float*)d_in[3];
    const float* b_in = (const float*)d_in[4];
    const float* W_h  = (const float*)d_in[5];
    const float* b_h  = (const float*)d_in[6];
    const float* W_r  = (const float*)d_in[7];
    const float* W_s  = (const float*)d_in[8];
    const float* W_o  = (const float*)d_in[9];
    const float* b_o  = (const float*)d_in[10];
    float* out = (float*)d_out;

    static cudaStream_t sB = nullptr;
    static cudaEvent_t ePack, eWr[7];
    if (!sB) {
        cudaStreamCreateWithFlags(&sB, cudaStreamNonBlocking);
        cudaEventCreateWithFlags(&ePack, cudaEventDisableTiming);
        for (int k = 0; k < 7; k++)
            cudaEventCreateWithFlags(&eWr[k], cudaEventDisableTiming);
        cudaFuncSetAttribute(Wr_kernel,
            cudaFuncAttributeMaxDynamicSharedMemorySize, (int)SMP_BYTES);
        cudaFuncSetAttribute(Lp_kernel,
            cudaFuncAttributeMaxDynamicSharedMemorySize, (int)SMP_BYTES);
    }

    // main: init + prelayer (bias/input, mask-free) + pack (adj -> bits)
    init_kernel<<<256, 256>>>(b_in, b_h);
    prelayer_kernel<<<128, 256>>>(x, W_in);
    pack_kernel<<<Nn, 256>>>(adj);
    cudaEventRecord(ePack, 0);

    // stream B: all h @ Wr work (independent of the layer chain)
    cudaStreamWaitEvent(sB, ePack, 0);
    for (int k = 0; k < 7; k++) {
        Wr_kernel<<<dim3(8, (7 - k) * 8), 256, SMP_BYTES, sB>>>(W_r, h, k);
        cudaEventRecord(eWr[k], sB);
    }

    // main: serial layer chain; joins B progressively via eWr[j]
    for (int j = 0; j < 7; j++) {
        int nch = (j <= 4) ? 4 : 2;          // tail layers: more blocks
        int ksl = 1024 / (32 * nch);
        cudaStreamWaitEvent(0, eWr[j], 0);   // pre[j] complete
        Lp_kernel<<<dim3(8, (7 - j) * ksl), 256, SMP_BYTES>>>(W_h, W_s, j, nch, ksl);
    }

    final_kernel<<<8, 256>>>(W_o, b_o, out);
}

// round 15
// speedup vs baseline: 1.0713x; 1.0713x over previous
#include <cuda_runtime.h>
#include <cuda_fp16.h>
#include <cstdint>

#define Nn 8192
#define Dd 1024

// Persistent scratch. g_pre[j] = PRE-activation of skips[j], j=0..7.
__device__ float g_pre[8][32][Dd];

#define APW 20   // uint32 words per fp16 tile row (16 data + 4 pad)

// Dynamic-smem workspace (49408 B -> 4 blocks/SM).
struct SmemP {
    uint32_t Ah[128 * APW];        // masked W, single fp16 plane   10240 B
    uint32_t Bh[32 * APW];         // X hi plane                     2560 B
    uint32_t Bl[32 * APW];         // X lo plane                     2560 B
    uint32_t kbit[2][32 * 5];      // ballot masks per buffer        1280 B
    float    Wraw[2][128 * 32];    // raw W tiles (cp.async dst)    32768 B
};
#define SMP_BYTES sizeof(SmemP)

__device__ __forceinline__ float sig(float v) {
    return 1.f / (1.f + __expf(-v));
}
__device__ __forceinline__ void redadd(float* p, float v) {
    asm volatile("red.global.add.f32 [%0], %1;" :: "l"(p), "f"(v) : "memory");
}
__device__ __forceinline__ uint32_t s2u(const void* p) {
    return (uint32_t)__cvta_generic_to_shared(p);
}
__device__ __forceinline__ void cpa16(uint32_t dst, const void* src) {
    asm volatile("cp.async.cg.shared.global [%0], [%1], 16;" :: "r"(dst), "l"(src));
}
// pack two floats to fp16x2 (e0 -> low half, e1 -> high half)
__device__ __forceinline__ uint32_t pk2h(float e1, float e0) {
    uint32_t r;
    asm("cvt.rn.f16x2.f32 %0, %1, %2;" : "=r"(r) : "f"(e1), "f"(e0));
    return r;
}
__device__ __forceinline__ float h_lo(uint32_t r) {
    return __half2float(__ushort_as_half((unsigned short)(r & 0xFFFFu)));
}
__device__ __forceinline__ float h_hi(uint32_t r) {
    return __half2float(__ushort_as_half((unsigned short)(r >> 16)));
}

// D += A(f16) * B(f16), m16n8k16, fp32 accumulate
__device__ __forceinline__ void mma16h(float* c,
                                       uint32_t a0, uint32_t a1, uint32_t a2, uint32_t a3,
                                       uint32_t b0, uint32_t b1) {
    asm volatile("mma.sync.aligned.m16n8k16.row.col.f32.f16.f16.f32 "
                 "{%0,%1,%2,%3}, {%4,%5,%6,%7}, {%8,%9}, {%0,%1,%2,%3};"
                 : "+f"(c[0]), "+f"(c[1]), "+f"(c[2]), "+f"(c[3])
                 : "r"(a0), "r"(a1), "r"(a2), "r"(a3), "r"(b0), "r"(b1));
}

// ---------------------------------------------------------------------------
// Masked matvec via mma.sync: W single fp16 plane, X fp16 hi/lo split
// (2 products; only W's fp16 rounding remains, rel err ~2^-12):
//   out[b, d0+d] += sum_n act(X[b,n]) * W[d0+d,n] * (adjA[n*Nn + d0+d] != 0)
// Block 256 threads (8 warps), tile M=128 x N=32, K chunks of 32, pipelined.
// ---------------------------------------------------------------------------
template <bool SIG>
__device__ __forceinline__ void mv_mma(
    SmemP* sm,
    const float* __restrict__ W, int wstride,
    const int* __restrict__ adjA,
    const float* __restrict__ X, int xstride,
    float* __restrict__ out,
    int d0, int n0, int nchunks)
{
    const int tid  = threadIdx.x;
    const int wid  = tid >> 5, lane = tid & 31;
    const int g    = lane >> 2, tg = lane & 3;
    const int mw   = wid * 16;
    const int kq   = tid & 7;
    const int dw   = tid >> 3;
    const int jc   = dw & 3;
    const int bsh  = dw >> 2;

    float c[4][4];
#pragma unroll
    for (int i = 0; i < 4; i++)
#pragma unroll
        for (int q = 0; q < 4; q++) c[i][q] = 0.f;

    int4   areg[4];
    float4 xcur, xnext;

    {   // prologue: chunk 0 (W cp.async; adj ballots; X LDG)
        const int nb = n0;
#pragma unroll
        for (int p = 0; p < 4; p++) {
            int d = p * 32 + dw;
            cpa16(s2u(&sm->Wraw[0][d * 32 + kq * 4]),
                  &W[(size_t)(d0 + d) * wstride + nb + kq * 4]);
        }
        asm volatile("cp.async.commit_group;");
#pragma unroll
        for (int q = 0; q < 4; q++) {
            int k = q * 8 + wid;
            areg[q] = *(const int4*)&adjA[(size_t)(nb + k) * Nn + d0 + lane * 4];
        }
        xcur = *(const float4*)&X[(size_t)dw * xstride + nb + kq * 4];
#pragma unroll
        for (int q = 0; q < 4; q++) {
            int k = q * 8 + wid;
            uint32_t b0 = __ballot_sync(0xFFFFFFFFu, areg[q].x != 0);
            uint32_t b1 = __ballot_sync(0xFFFFFFFFu, areg[q].y != 0);
            uint32_t b2 = __ballot_sync(0xFFFFFFFFu, areg[q].z != 0);
            uint32_t b3 = __ballot_sync(0xFFFFFFFFu, areg[q].w != 0);
            if (lane < 4) {
                uint32_t v = (lane == 0) ? b0 : (lane == 1) ? b1
                           : (lane == 2) ? b2 : b3;
                sm->kbit[0][k * 5 + lane] = v;
            }
        }
    }

    for (int ch = 0; ch < nchunks; ch++) {
        const int buf = ch & 1;
        const bool more = (ch + 1 < nchunks);

        // ---- issue chunk c+1 loads (W cp.async, adj LDG, X LDG) ----
        if (more) {
            const int nb2 = n0 + (ch + 1) * 32;
#pragma unroll
            for (int p = 0; p < 4; p++) {
                int d = p * 32 + dw;
                cpa16(s2u(&sm->Wraw[buf ^ 1][d * 32 + kq * 4]),
                      &W[(size_t)(d0 + d) * wstride + nb2 + kq * 4]);
            }
            asm volatile("cp.async.commit_group;");
#pragma unroll
            for (int q = 0; q < 4; q++) {
                int k = q * 8 + wid;
                areg[q] = *(const int4*)&adjA[(size_t)(nb2 + k) * Nn + d0 + lane * 4];
            }
            xnext = *(const float4*)&X[(size_t)dw * xstride + nb2 + kq * 4];
            asm volatile("cp.async.wait_group 1;");
        } else {
            asm volatile("cp.async.wait_group 0;");
        }
        __syncthreads();   // W[ch] landed; prev MMA done; kbit[buf] ready

        // ---- staging: mask raw W via kbit, convert to single fp16 plane ----
        uint32_t m0 = sm->kbit[buf][(kq * 4 + 0) * 5 + jc];
        uint32_t m1 = sm->kbit[buf][(kq * 4 + 1) * 5 + jc];
        uint32_t m2 = sm->kbit[buf][(kq * 4 + 2) * 5 + jc];
        uint32_t m3 = sm->kbit[buf][(kq * 4 + 3) * 5 + jc];
#pragma unroll
        for (int p = 0; p < 4; p++) {
            int d = p * 32 + dw;
            int bp = p * 8 + bsh;
            float4 w = *(const float4*)&sm->Wraw[buf][d * 32 + kq * 4];
            if (!((m0 >> bp) & 1u)) w.x = 0.f;
            if (!((m1 >> bp) & 1u)) w.y = 0.f;
            if (!((m2 >> bp) & 1u)) w.z = 0.f;
            if (!((m3 >> bp) & 1u)) w.w = 0.f;
            *(uint2*)&sm->Ah[d * APW + kq * 2] =
                make_uint2(pk2h(w.y, w.x), pk2h(w.w, w.z));
        }
        // X: activation, fp16 hi/lo split (exact fp32 X across 2 products)
        {
            float4 xv = xcur;
            if (SIG) {
                xv.x = sig(xv.x); xv.y = sig(xv.y);
                xv.z = sig(xv.z); xv.w = sig(xv.w);
            }
            uint32_t h01 = pk2h(xv.y, xv.x);
            uint32_t h23 = pk2h(xv.w, xv.z);
            float l0 = xv.x - h_lo(h01), l1 = xv.y - h_hi(h01);
            float l2 = xv.z - h_lo(h23), l3 = xv.w - h_hi(h23);
            *(uint2*)&sm->Bh[dw * APW + kq * 2] = make_uint2(h01, h23);
            *(uint2*)&sm->Bl[dw * APW + kq * 2] =
                make_uint2(pk2h(l1, l0), pk2h(l3, l2));
        }
        __syncthreads();

        // ---- MMA phase: 2 k16-steps x 4 n-tiles x (A*Bh + A*Bl) ----
#pragma unroll
        for (int ks = 0; ks < 2; ks++) {
            int u  = ks * 8 + tg;
            int r0 = (mw + g) * APW, r1 = (mw + g + 8) * APW;
            uint32_t a0 = sm->Ah[r0 + u],     a1 = sm->Ah[r1 + u];
            uint32_t a2 = sm->Ah[r0 + u + 4], a3 = sm->Ah[r1 + u + 4];
#pragma unroll
            for (int nt = 0; nt < 4; nt++) {
                int bb = (nt * 8 + g) * APW + u;
                uint32_t bh0 = sm->Bh[bb], bh1 = sm->Bh[bb + 4];
                uint32_t bl0 = sm->Bl[bb], bl1 = sm->Bl[bb + 4];
                mma16h(c[nt], a0, a1, a2, a3, bh0, bh1);
                mma16h(c[nt], a0, a1, a2, a3, bl0, bl1);
            }
        }

        // ---- compress next chunk's adj to ballots; rotate X ----
        if (more) {
#pragma unroll
            for (int q = 0; q < 4; q++) {
                int k = q * 8 + wid;
                uint32_t b0 = __ballot_sync(0xFFFFFFFFu, areg[q].x != 0);
                uint32_t b1 = __ballot_sync(0xFFFFFFFFu, areg[q].y != 0);
                uint32_t b2 = __ballot_sync(0xFFFFFFFFu, areg[q].z != 0);
                uint32_t b3 = __ballot_sync(0xFFFFFFFFu, areg[q].w != 0);
                if (lane < 4) {
                    uint32_t v = (lane == 0) ? b0 : (lane == 1) ? b1
                               : (lane == 2) ? b2 : b3;
                    sm->kbit[buf ^ 1][k * 5 + lane] = v;
                }
            }
            xcur = xnext;
        }
    }

    // epilogue: C m16n8: c0:(g,2tg) c1:(g,2tg+1) c2:(g+8,2tg) c3:(g+8,2tg+1)
    const int drow = d0 + mw + g;
#pragma unroll
    for (int nt = 0; nt < 4; nt++) {
        int b = nt * 8 + 2 * tg;
        redadd(&out[(size_t)b       * Dd + drow],     c[nt][0]);
        redadd(&out[(size_t)(b + 1) * Dd + drow],     c[nt][1]);
        redadd(&out[(size_t)b       * Dd + drow + 8], c[nt][2]);
        redadd(&out[(size_t)(b + 1) * Dd + drow + 8], c[nt][3]);
    }
}

// ---------------------------------------------------------------------------

// g_pre[0][b][:] = b_in; g_pre[i][b][:] = b_h[i-1] for i=1..7  (float4)
__global__ void init_kernel(const float* __restrict__ b_in,
                            const float* __restrict__ b_h) {
    int idx = blockIdx.x * 256 + threadIdx.x;   // 256 blocks -> 65536 float4
    int fd = idx & 255;
    int i = idx >> 13;
    const float4* src = (i == 0) ? (const float4*)b_in
                                 : (const float4*)(b_h + (size_t)(i - 1) * Dd);
    ((float4*)g_pre)[idx] = src[fd];
}

// pre[k] += h @ Wr_m(k).T  (n >= (k+1)*1024). grid (8, (7-k)*8), nch=4.
__global__ void __launch_bounds__(256, 4) Wr_kernel(
    const float* __restrict__ W_r, const int* __restrict__ adj,
    const float* __restrict__ h, int k)
{
    extern __shared__ __align__(16) char dsm[];
    mv_mma<false>((SmemP*)dsm, W_r + (size_t)k * Dd * Nn, Nn,
                  adj + k * Dd, h, Nn, &g_pre[k][0][0],
                  blockIdx.x * 128, (k + 1) * 1024 + blockIdx.y * 128, 4);
}

// g_pre[0] += x @ W_in.T  (atomic; overlaps freely)
__global__ void prelayer_kernel(
    const float* __restrict__ x, const float* __restrict__ W_in)
{
    int idx = blockIdx.x * 256 + threadIdx.x;  // 32768
    int d = idx & 1023, bt = idx >> 10;
    const float4* xr = (const float4*)(x + bt * 256);
    const float4* wr = (const float4*)(W_in + (size_t)d * 256);
    float s = 0.f;
#pragma unroll 8
    for (int c = 0; c < 64; c++) {
        float4 aa = xr[c], bb = wr[c];
        s += aa.x * bb.x + aa.y * bb.y + aa.z * bb.z + aa.w * bb.w;
    }
    redadd(&g_pre[0][bt][d], s);
}

// Serial-chain launch after pre[j] complete. grid (8, (7-j)*ksl):
//   g == 0        : pre[j+1] += sig(pre[j]) @ Wh_m(j).T
//   g in [1, 7-j) : pre[i+1] += sig(pre[j]) @ Ws-block(i, j).T  (i = j+g)
__global__ void __launch_bounds__(256, 4) Lp_kernel(
    const float* __restrict__ W_h, const float* __restrict__ W_s,
    const int* __restrict__ adj, int j, int nch, int ksl)
{
    extern __shared__ __align__(16) char dsm[];
    SmemP* sm = (SmemP*)dsm;
    int d0 = blockIdx.x * 128;
    int g = blockIdx.y / ksl;
    int nloc = (blockIdx.y % ksl) * 32 * nch;
    if (g == 0) {
        mv_mma<true>(sm, W_h + (size_t)j * Dd * Dd, Dd,
                     adj + (size_t)j * Dd * Nn + (j + 1) * Dd,
                     &g_pre[j][0][0], Dd,
                     &g_pre[j + 1][0][0], d0, nloc, nch);
    } else {
        int i = j + g;
        // X rebased so X[b*Dd + n] == g_pre[j][b][n - j*1024]
        mv_mma<true>(sm, W_s + (size_t)(i - 1) * Dd * 6144, 6144,
                     adj + (i + 1) * Dd,
                     &g_pre[j][0][0] - j * 1024, Dd,
                     &g_pre[i + 1][0][0], d0, j * 1024 + nloc, nch);
    }
}

// out = sig(g_pre[7]) @ W_o.T + b_o
__global__ void final_kernel(const float* __restrict__ W_o,
                             const float* __restrict__ b_o,
                             float* __restrict__ out)
{
    int idx = blockIdx.x * 256 + threadIdx.x;  // 2048
    int o = idx & 63, bt = idx >> 6;
    const float4* sr = (const float4*)&g_pre[7][bt][0];
    const float4* wr = (const float4*)(W_o + (size_t)o * Dd);
    float s = 0.f;
#pragma unroll 8
    for (int c = 0; c < 256; c++) {
        float4 aa = sr[c], bb = wr[c];
        s += sig(aa.x) * bb.x + sig(aa.y) * bb.y + sig(aa.z) * bb.z + sig(aa.w) * bb.w;
    }
    out[bt * 64 + o] = s + b_o[o];
}

// ---------------------------------------------------------------------------

extern "C" void kernel_launch(void* const* d_in, const int* in_sizes, int n_in,
                              void* d_out, int out_size)
{
    const float* x    = (const float*)d_in[0];
    const float* h    = (const float*)d_in[1];
    const int*   adj  = (const int*)d_in[2];
    const float* W_in = (const float*)d_in[3];
    const float* b_in = (const float*)d_in[4];
    const float* W_h  = (const float*)d_in[5];
    const float* b_h  = (const float*)d_in[6];
    const float* W_r  = (const float*)d_in[7];
    const float* W_s  = (const float*)d_in[8];
    const float* W_o  = (const float*)d_in[9];
    const float* b_o  = (const float*)d_in[10];
    float* out = (float*)d_out;

    static cudaStream_t sB = nullptr;
    static cudaEvent_t eInit, eWr[7];
    if (!sB) {
        cudaStreamCreateWithFlags(&sB, cudaStreamNonBlocking);
        cudaEventCreateWithFlags(&eInit, cudaEventDisableTiming);
        for (int k = 0; k < 7; k++)
            cudaEventCreateWithFlags(&eWr[k], cudaEventDisableTiming);
        cudaFuncSetAttribute(Wr_kernel,
            cudaFuncAttributeMaxDynamicSharedMemorySize, (int)SMP_BYTES);
        cudaFuncSetAttribute(Lp_kernel,
            cudaFuncAttributeMaxDynamicSharedMemorySize, (int)SMP_BYTES);
    }

    // main stream: init + prelayer; fork stream B for all h @ Wr work
    init_kernel<<<256, 256>>>(b_in, b_h);
    cudaEventRecord(eInit, 0);
    cudaStreamWaitEvent(sB, eInit, 0);
    for (int k = 0; k < 7; k++) {
        Wr_kernel<<<dim3(8, (7 - k) * 8), 256, SMP_BYTES, sB>>>(W_r, adj, h, k);
        cudaEventRecord(eWr[k], sB);
    }
    prelayer_kernel<<<128, 256>>>(x, W_in);

    // serial layer chain on the main stream; joins B progressively
    for (int j = 0; j < 7; j++) {
        int nch = (j <= 4) ? 4 : 2;          // tail layers: more blocks
        int ksl = 1024 / (32 * nch);
        cudaStreamWaitEvent(0, eWr[j], 0);   // pre[j] complete
        Lp_kernel<<<dim3(8, (7 - j) * ksl), 256, SMP_BYTES>>>(
            W_h, W_s, adj, j, nch, ksl);
    }

    final_kernel<<<8, 256>>>(W_o, b_o, out);
}